// round 12
// baseline (speedup 1.0000x reference)
#include <cuda_runtime.h>
#include <cstdint>
#include <cstddef>

// ---------------------------------------------------------------------------
// EncoderDecoder LSTM, GB300 sm_103a.
//   V=32000, E=512 (!!), H=1024, T=4096
// Round-9 bug: E was hardcoded as 1024; pre-projection GEMMs read emb/Wih
// with the wrong row stride. Fixed: GEMM takes K as a parameter.
// 4 graph nodes:
//   1) gemm_nt K=512 : enc_pre = Wih @ emb[seq] + bih + bhh   [4096, 4096]
//   2) gemm_nt K=512 : dec_pre = Wih @ emb[seq[:-1]] + biases [4095, 4096]
//   3) persistent recurrence (register-resident Whh, grid barrier)
//   4) gemm_nt K=1024: logits = dec_h @ out_W^T + out_b       [4095, 32000]
// ---------------------------------------------------------------------------

#define T_SEQ 4096
#define TD    (T_SEQ - 1)
#define EMB   512                  // E  (the constant that was wrong)
#define HID   1024                 // H
#define G4H   4096                 // 4*H
#define VOC   32000
#define NB    128
#define NSTEP (T_SEQ + TD)

__device__ __align__(128) float g_encpre[(size_t)T_SEQ * G4H];
__device__ __align__(128) float g_decpre[(size_t)TD * G4H];
__device__ __align__(128) float g_hh[(size_t)(NSTEP + 1) * HID];
__device__ unsigned g_barcnt = 0;
__device__ unsigned g_bargen = 0;

__device__ __forceinline__ float sigm(float x) {
    return 1.0f / (1.0f + __expf(-x));
}
__device__ __forceinline__ float tanh_acc(float x) {
    float ax = fabsf(x);
    float t  = __expf(-2.0f * ax);
    float r  = (1.0f - t) / (1.0f + t);
    return x < 0.0f ? -r : r;
}

__device__ __forceinline__ void gridbar() {
    __syncthreads();
    if (threadIdx.x == 0) {
        __threadfence();
        unsigned gen = atomicAdd(&g_bargen, 0u);
        if (atomicAdd(&g_barcnt, 1u) == NB - 1u) {
            atomicExch(&g_barcnt, 0u);
            __threadfence();
            atomicAdd(&g_bargen, 1u);
        } else {
            while (atomicAdd(&g_bargen, 0u) == gen) { __nanosleep(32); }
        }
        __threadfence();
    }
    __syncthreads();
}

// ------------------------- persistent recurrence (verified core) -----------
// Warp w owns gate row grow(w) = (w>>3)*H + 8b + (w&7); lane holds
// Whh[grow][lane + 32*j], j = 0..31, in registers.
__device__ __forceinline__ void load_wreg(
    const float* __restrict__ W, float (&wreg)[32], int grow, int lane)
{
#pragma unroll
    for (int j = 0; j < 32; j++)
        wreg[j] = __ldg(&W[(size_t)grow * HID + lane + 32 * j]);
}

__global__ void __launch_bounds__(1024, 1)
lstm_rec_kernel(const float* __restrict__ encWhh,
                const float* __restrict__ decWhh)
{
    __shared__ float hs[HID];
    __shared__ float gv[32];

    const int b    = blockIdx.x;
    const int tid  = threadIdx.x;
    const int w    = tid >> 5;
    const int lane = tid & 31;
    const int grow = (w >> 3) * HID + b * 8 + (w & 7);

    float wreg[32];
    load_wreg(encWhh, wreg, grow, lane);

    float c = 0.0f;
    if (tid < 8)
        *(volatile float*)&g_hh[b * 8 + tid] = 0.0f;
    __threadfence();
    gridbar();

    for (int s = 0; s < NSTEP; s++) {
        if (s == T_SEQ)
            load_wreg(decWhh, wreg, grow, lane);

        hs[tid] = *(volatile const float*)&g_hh[(size_t)s * HID + tid];
        __syncthreads();

        float acc = 0.0f;
#pragma unroll
        for (int j = 0; j < 32; j++)
            acc = fmaf(wreg[j], hs[lane + 32 * j], acc);
#pragma unroll
        for (int o = 16; o; o >>= 1)
            acc += __shfl_xor_sync(0xffffffffu, acc, o);
        if (lane == 0) gv[w] = acc;
        __syncthreads();

        if (tid < 8) {
            const float* pre = (s < T_SEQ)
                ? g_encpre + (size_t)s * G4H
                : g_decpre + (size_t)(s - T_SEQ) * G4H;
            int u = b * 8 + tid;
            float vi = gv[tid]      + __ldg(&pre[u]);
            float vf = gv[8 + tid]  + __ldg(&pre[HID + u]);
            float vg = gv[16 + tid] + __ldg(&pre[2 * HID + u]);
            float vo = gv[24 + tid] + __ldg(&pre[3 * HID + u]);
            float ii = sigm(vi);
            float ff = sigm(vf);
            float gg = tanh_acc(vg);
            float oo = sigm(vo);
            c = ff * c + ii * gg;
            *(volatile float*)&g_hh[(size_t)(s + 1) * HID + u]
                = oo * tanh_acc(c);
            __threadfence();
        }
        gridbar();
    }
}

// ------------------------- tiled fp32 GEMM: C = A(rows) @ B^T + bias -------
// A: [M, K] row-major (optionally row-gathered); B: [N, K] row-major.
// K is a runtime parameter (512 for pre-projections, 1024 for logits);
// requires K % 16 == 0, N % 128 == 0.
// 128x128 tile, BK=16, 256 threads, 8x8 microtile, float4 global loads.
__global__ void __launch_bounds__(256)
gemm_nt_kernel(const float* __restrict__ A, const int* __restrict__ gather,
               const float* __restrict__ B, const float* __restrict__ bias,
               const float* __restrict__ bias2, float* __restrict__ C,
               int M, int N, int K)
{
    __shared__ float As[16][132];
    __shared__ float Bs[16][132];

    const int n0  = blockIdx.x * 128;
    const int m0  = blockIdx.y * 128;
    const int tid = threadIdx.x;
    const int tx  = tid & 15;
    const int ty  = tid >> 4;

    float acc[8][8];
#pragma unroll
    for (int i = 0; i < 8; i++)
#pragma unroll
        for (int j = 0; j < 8; j++) acc[i][j] = 0.0f;

    for (int k0 = 0; k0 < K; k0 += 16) {
#pragma unroll
        for (int i = 0; i < 2; i++) {
            int f  = tid + i * 256;          // 0..511 float4 slots
            int m  = f >> 2;                 // 0..127
            int kq = f & 3;                  // float4 within the 16-wide k
            int gm = m0 + m;
            int row = (gm < M) ? gm : (M - 1);
            if (gather) row = __ldg(&gather[row]);
            float4 v = *reinterpret_cast<const float4*>(
                A + (size_t)row * K + k0 + kq * 4);
            if (gm >= M) v = make_float4(0.f, 0.f, 0.f, 0.f);
            As[kq * 4 + 0][m] = v.x;
            As[kq * 4 + 1][m] = v.y;
            As[kq * 4 + 2][m] = v.z;
            As[kq * 4 + 3][m] = v.w;
        }
#pragma unroll
        for (int i = 0; i < 2; i++) {
            int f  = tid + i * 256;
            int n  = f >> 2;
            int kq = f & 3;
            float4 v = *reinterpret_cast<const float4*>(
                B + (size_t)(n0 + n) * K + k0 + kq * 4);
            Bs[kq * 4 + 0][n] = v.x;
            Bs[kq * 4 + 1][n] = v.y;
            Bs[kq * 4 + 2][n] = v.z;
            Bs[kq * 4 + 3][n] = v.w;
        }
        __syncthreads();

#pragma unroll
        for (int kk = 0; kk < 16; kk++) {
            float a[8], bb[8];
#pragma unroll
            for (int i = 0; i < 8; i++) a[i]  = As[kk][ty * 8 + i];
#pragma unroll
            for (int j = 0; j < 8; j++) bb[j] = Bs[kk][tx * 8 + j];
#pragma unroll
            for (int i = 0; i < 8; i++)
#pragma unroll
                for (int j = 0; j < 8; j++)
                    acc[i][j] = fmaf(a[i], bb[j], acc[i][j]);
        }
        __syncthreads();
    }

#pragma unroll
    for (int i = 0; i < 8; i++) {
        int m = m0 + ty * 8 + i;
        if (m < M) {
#pragma unroll
            for (int j = 0; j < 8; j++) {
                int n = n0 + tx * 8 + j;
                float bv = bias ? __ldg(&bias[n]) : 0.0f;
                if (bias2) bv += __ldg(&bias2[n]);
                C[(size_t)m * N + n] = acc[i][j] + bv;
            }
        }
    }
}

// ------------------------- launch ------------------------------------------
extern "C" void kernel_launch(void* const* d_in, const int* in_sizes, int n_in,
                              void* d_out, int out_size)
{
    (void)in_sizes; (void)n_in; (void)out_size;
    const int*   seq     = (const int*)  d_in[0];
    const float* enc_emb = (const float*)d_in[1];   // [V, 512]
    const float* enc_Wih = (const float*)d_in[2];   // [4096, 512]
    const float* enc_Whh = (const float*)d_in[3];   // [4096, 1024]
    const float* enc_bih = (const float*)d_in[4];
    const float* enc_bhh = (const float*)d_in[5];
    const float* dec_emb = (const float*)d_in[6];   // [V, 512]
    const float* dec_Wih = (const float*)d_in[7];   // [4096, 512]
    const float* dec_Whh = (const float*)d_in[8];   // [4096, 1024]
    const float* dec_bih = (const float*)d_in[9];
    const float* dec_bhh = (const float*)d_in[10];
    const float* out_W   = (const float*)d_in[11];  // [32000, 1024]
    const float* out_b   = (const float*)d_in[12];  // [32000]
    float*       out     = (float*)d_out;

    void *p_encpre = nullptr, *p_decpre = nullptr, *p_hh = nullptr;
    cudaGetSymbolAddress(&p_encpre, g_encpre);
    cudaGetSymbolAddress(&p_decpre, g_decpre);
    cudaGetSymbolAddress(&p_hh,     g_hh);

    // 1) encoder input projection (K = E = 512)
    {
        dim3 grid(G4H / 128, (T_SEQ + 127) / 128);
        gemm_nt_kernel<<<grid, 256>>>(enc_emb, seq, enc_Wih, enc_bih, enc_bhh,
                                      (float*)p_encpre, T_SEQ, G4H, EMB);
    }
    // 2) decoder input projection (teacher forcing: seq[0..T-2], K = 512)
    {
        dim3 grid(G4H / 128, (TD + 127) / 128);
        gemm_nt_kernel<<<grid, 256>>>(dec_emb, seq, dec_Wih, dec_bih, dec_bhh,
                                      (float*)p_decpre, TD, G4H, EMB);
    }
    // 3) persistent recurrence (H = 1024, unchanged)
    lstm_rec_kernel<<<NB, 1024>>>(enc_Whh, dec_Whh);

    // 4) logits = dec_h @ out_W^T + out_b  (K = H = 1024)
    {
        const float* dech = (const float*)p_hh + (size_t)(T_SEQ + 1) * HID;
        dim3 grid(VOC / 128, (TD + 127) / 128);
        gemm_nt_kernel<<<grid, 256>>>(dech, nullptr, out_W,
                                      out_b, nullptr, out, TD, VOC, HID);
    }
}

// round 15
// speedup vs baseline: 1.3675x; 1.3675x over previous
#include <cuda_runtime.h>
#include <cstdint>
#include <cstddef>

// ---------------------------------------------------------------------------
// EncoderDecoder LSTM, GB300 sm_103a.   V=32000, E=512, H=1024, T=4096
// 5 graph nodes:
//   1) gemm_nt K=512 : enc_pre = Wih @ emb[seq] + bih + bhh   [4096, 4096]
//   2) gemm_nt K=512 : dec_pre = Wih @ emb[seq[:-1]] + biases [4095, 4096]
//   3) init: zero per-step done counters
//   4) persistent recurrence — register-resident Whh; per-step monotonic
//      done-counter sync (release: fence+atomicAdd, acquire: ld.acquire.gpu)
//   5) gemm_nt K=1024: logits = dec_h @ out_W^T + out_b       [4095, 32000]
// R13 bug fixed here: the poll was a WEAK load with no reader-side acquire;
// h loads could be satisfied stale. Poll is now ld.global.acquire.gpu.
// ---------------------------------------------------------------------------

#define T_SEQ 4096
#define TD    (T_SEQ - 1)
#define EMB   512
#define HID   1024
#define G4H   4096
#define VOC   32000
#define NB    128
#define NSTEP (T_SEQ + TD)

__device__ __align__(128) float g_encpre[(size_t)T_SEQ * G4H];
__device__ __align__(128) float g_decpre[(size_t)TD * G4H];
// write-once h history: g_hh[s] = h after s steps; decoder h_t at s=4097+t
__device__ __align__(128) float g_hh[(size_t)(NSTEP + 1) * HID];
// monotonic per-step arrival counters (zeroed by init kernel each replay)
__device__ __align__(128) int   g_done[NSTEP + 1];

__device__ __forceinline__ float sigm(float x) {
    return 1.0f / (1.0f + __expf(-x));
}
__device__ __forceinline__ float tanh_acc(float x) {
    float ax = fabsf(x);
    float t  = __expf(-2.0f * ax);
    float r  = (1.0f - t) / (1.0f + t);
    return x < 0.0f ? -r : r;
}

// ------------------------- init: zero done counters ------------------------
__global__ void rec_init_kernel()
{
    int i = blockIdx.x * blockDim.x + threadIdx.x;
    if (i <= NSTEP) g_done[i] = 0;
}

// ------------------------- persistent recurrence ---------------------------
// CTA b owns hidden units [8b, 8b+8); warp w owns gate row
// grow(w) = (w>>3)*H + 8b + (w&7); lane holds Whh[grow][lane+32j] in regs.
__device__ __forceinline__ void load_wreg(
    const float* __restrict__ W, float (&wreg)[32], int grow, int lane)
{
#pragma unroll
    for (int j = 0; j < 32; j++)
        wreg[j] = __ldg(&W[(size_t)grow * HID + lane + 32 * j]);
}

__global__ void __launch_bounds__(1024, 1)
lstm_rec_kernel(const float* __restrict__ encWhh,
                const float* __restrict__ decWhh)
{
    __shared__ float hs[HID];
    __shared__ float gv[32];

    const int b    = blockIdx.x;
    const int tid  = threadIdx.x;
    const int w    = tid >> 5;
    const int lane = tid & 31;
    const int grow = (w >> 3) * HID + b * 8 + (w & 7);

    float wreg[32];
    load_wreg(encWhh, wreg, grow, lane);

    float c = 0.0f;

    // publish h_0 = 0 for our 8 units, then arrive at done[0]
    if (tid < 8)
        __stcg(&g_hh[b * 8 + tid], 0.0f);
    __threadfence();
    __syncthreads();
    if (tid == 0) atomicAdd(&g_done[0], 1);

    for (int s = 0; s < NSTEP; s++) {
        if (s == T_SEQ)
            load_wreg(decWhh, wreg, grow, lane);

        // ACQUIRE poll: wait until all 128 CTAs have published h_s.
        // ld.acquire.gpu orders all our subsequent loads after the
        // observation; __syncthreads extends that to the whole CTA.
        if (tid == 0) {
            int d;
            do {
                asm volatile("ld.global.acquire.gpu.b32 %0, [%1];"
                             : "=r"(d) : "l"(&g_done[s]) : "memory");
            } while (d < NB);
        }
        __syncthreads();

        hs[tid] = __ldcg(&g_hh[(size_t)s * HID + tid]);
        __syncthreads();

        // warp w: dot(Whh[grow], h_s)
        float acc = 0.0f;
#pragma unroll
        for (int j = 0; j < 32; j++)
            acc = fmaf(wreg[j], hs[lane + 32 * j], acc);
#pragma unroll
        for (int o = 16; o; o >>= 1)
            acc += __shfl_xor_sync(0xffffffffu, acc, o);
        if (lane == 0) gv[w] = acc;
        __syncthreads();

        // warp 0 finishes: gates, cell update, publish h_{s+1}, arrive
        if (w == 0) {
            if (lane < 8) {
                const float* pre = (s < T_SEQ)
                    ? g_encpre + (size_t)s * G4H
                    : g_decpre + (size_t)(s - T_SEQ) * G4H;
                int u = b * 8 + lane;
                float vi = gv[lane]      + __ldg(&pre[u]);
                float vf = gv[8 + lane]  + __ldg(&pre[HID + u]);
                float vg = gv[16 + lane] + __ldg(&pre[2 * HID + u]);
                float vo = gv[24 + lane] + __ldg(&pre[3 * HID + u]);
                float ii = sigm(vi);
                float ff = sigm(vf);
                float gg = tanh_acc(vg);
                float oo = sigm(vo);
                c = ff * c + ii * gg;
                __stcg(&g_hh[(size_t)(s + 1) * HID + u], oo * tanh_acc(c));
                __threadfence();         // release: h before arrival
            }
            __syncwarp();
            if (lane == 0) atomicAdd(&g_done[s + 1], 1);
        }
        // non-writer warps proceed; next iteration's acquire-poll +
        // __syncthreads gates them before hs is overwritten.
    }
}

// ------------------------- tiled fp32 GEMM: C = A(rows) @ B^T + bias -------
// A: [M, K] row-major (optionally row-gathered); B: [N, K] row-major.
// K runtime (512 pre / 1024 logits); K%16==0, N%128==0.
__global__ void __launch_bounds__(256)
gemm_nt_kernel(const float* __restrict__ A, const int* __restrict__ gather,
               const float* __restrict__ B, const float* __restrict__ bias,
               const float* __restrict__ bias2, float* __restrict__ C,
               int M, int N, int K)
{
    __shared__ float As[16][132];
    __shared__ float Bs[16][132];

    const int n0  = blockIdx.x * 128;
    const int m0  = blockIdx.y * 128;
    const int tid = threadIdx.x;
    const int tx  = tid & 15;
    const int ty  = tid >> 4;

    float acc[8][8];
#pragma unroll
    for (int i = 0; i < 8; i++)
#pragma unroll
        for (int j = 0; j < 8; j++) acc[i][j] = 0.0f;

    for (int k0 = 0; k0 < K; k0 += 16) {
#pragma unroll
        for (int i = 0; i < 2; i++) {
            int f  = tid + i * 256;
            int m  = f >> 2;
            int kq = f & 3;
            int gm = m0 + m;
            int row = (gm < M) ? gm : (M - 1);
            if (gather) row = __ldg(&gather[row]);
            float4 v = *reinterpret_cast<const float4*>(
                A + (size_t)row * K + k0 + kq * 4);
            if (gm >= M) v = make_float4(0.f, 0.f, 0.f, 0.f);
            As[kq * 4 + 0][m] = v.x;
            As[kq * 4 + 1][m] = v.y;
            As[kq * 4 + 2][m] = v.z;
            As[kq * 4 + 3][m] = v.w;
        }
#pragma unroll
        for (int i = 0; i < 2; i++) {
            int f  = tid + i * 256;
            int n  = f >> 2;
            int kq = f & 3;
            float4 v = *reinterpret_cast<const float4*>(
                B + (size_t)(n0 + n) * K + k0 + kq * 4);
            Bs[kq * 4 + 0][n] = v.x;
            Bs[kq * 4 + 1][n] = v.y;
            Bs[kq * 4 + 2][n] = v.z;
            Bs[kq * 4 + 3][n] = v.w;
        }
        __syncthreads();

#pragma unroll
        for (int kk = 0; kk < 16; kk++) {
            float a[8], bb[8];
#pragma unroll
            for (int i = 0; i < 8; i++) a[i]  = As[kk][ty * 8 + i];
#pragma unroll
            for (int j = 0; j < 8; j++) bb[j] = Bs[kk][tx * 8 + j];
#pragma unroll
            for (int i = 0; i < 8; i++)
#pragma unroll
                for (int j = 0; j < 8; j++)
                    acc[i][j] = fmaf(a[i], bb[j], acc[i][j]);
        }
        __syncthreads();
    }

#pragma unroll
    for (int i = 0; i < 8; i++) {
        int m = m0 + ty * 8 + i;
        if (m < M) {
#pragma unroll
            for (int j = 0; j < 8; j++) {
                int n = n0 + tx * 8 + j;
                float bv = bias ? __ldg(&bias[n]) : 0.0f;
                if (bias2) bv += __ldg(&bias2[n]);
                C[(size_t)m * N + n] = acc[i][j] + bv;
            }
        }
    }
}

// ------------------------- launch ------------------------------------------
extern "C" void kernel_launch(void* const* d_in, const int* in_sizes, int n_in,
                              void* d_out, int out_size)
{
    (void)in_sizes; (void)n_in; (void)out_size;
    const int*   seq     = (const int*)  d_in[0];
    const float* enc_emb = (const float*)d_in[1];   // [V, 512]
    const float* enc_Wih = (const float*)d_in[2];   // [4096, 512]
    const float* enc_Whh = (const float*)d_in[3];   // [4096, 1024]
    const float* enc_bih = (const float*)d_in[4];
    const float* enc_bhh = (const float*)d_in[5];
    const float* dec_emb = (const float*)d_in[6];
    const float* dec_Wih = (const float*)d_in[7];
    const float* dec_Whh = (const float*)d_in[8];
    const float* dec_bih = (const float*)d_in[9];
    const float* dec_bhh = (const float*)d_in[10];
    const float* out_W   = (const float*)d_in[11];  // [32000, 1024]
    const float* out_b   = (const float*)d_in[12];  // [32000]
    float*       out     = (float*)d_out;

    void *p_encpre = nullptr, *p_decpre = nullptr, *p_hh = nullptr;
    cudaGetSymbolAddress(&p_encpre, g_encpre);
    cudaGetSymbolAddress(&p_decpre, g_decpre);
    cudaGetSymbolAddress(&p_hh,     g_hh);

    // 1) encoder input projection (K = E = 512)
    {
        dim3 grid(G4H / 128, (T_SEQ + 127) / 128);
        gemm_nt_kernel<<<grid, 256>>>(enc_emb, seq, enc_Wih, enc_bih, enc_bhh,
                                      (float*)p_encpre, T_SEQ, G4H, EMB);
    }
    // 2) decoder input projection (teacher forcing, K = 512)
    {
        dim3 grid(G4H / 128, (TD + 127) / 128);
        gemm_nt_kernel<<<grid, 256>>>(dec_emb, seq, dec_Wih, dec_bih, dec_bhh,
                                      (float*)p_decpre, TD, G4H, EMB);
    }
    // 3) zero per-step arrival counters (fresh each graph replay)
    rec_init_kernel<<<(NSTEP + 1 + 255) / 256, 256>>>();

    // 4) persistent recurrence
    lstm_rec_kernel<<<NB, 1024>>>(enc_Whh, dec_Whh);

    // 5) logits = dec_h @ out_W^T + out_b  (K = H = 1024)
    {
        const float* dech = (const float*)p_hh + (size_t)(T_SEQ + 1) * HID;
        dim3 grid(VOC / 128, (TD + 127) / 128);
        gemm_nt_kernel<<<grid, 256>>>(dech, nullptr, out_W,
                                      out_b, nullptr, out, TD, VOC, HID);
    }
}